// round 14
// baseline (speedup 1.0000x reference)
#include <cuda_runtime.h>
#include <cuda_bf16.h>
#include <math.h>

// Problem constants (fixed by dataset: B=4, H=W=320)
#define H_DIM 320
#define W_DIM 320
#define B_DIM 4
#define TILE 32
#define HALO 8
#define SROWS (TILE + 2 * HALO)   // 48 mask rows
#define NBLK_X (W_DIM / TILE)     // 10
#define NBLK_Y (H_DIM / TILE)     // 10
#define NTILES (NBLK_X * NBLK_Y * B_DIM) // 400
#define NCTA 148                  // one persistent CTA per SM
#define N_TOTAL (B_DIM * H_DIM * W_DIM)
#define FP_SCALE 16777216.0       // 2^24 fixed point (associative int adds)

__device__ unsigned long long g_sum = 0ull;   // two's-complement signed Q24
__device__ unsigned int g_arrived = 0;

// Exact global fallback. `best` on entry must be a valid upper bound
// (a real seed distance, or INF). Searches all rings r >= HALO+1.
__device__ __noinline__ int global_ring_search(const int* __restrict__ targets,
                                               int planeOff, int gh, int gw, int best)
{
    for (int r = HALO + 1; r < H_DIM + W_DIM; ++r) {
        if (r * r >= best) break;
        const int rr = r * r;
        const int yT = gh - r, yB = gh + r;
        for (int dx = -r; dx <= r; ++dx) {
            int d2 = rr + dx * dx;
            if (d2 >= best) continue;
            int x = gw + dx;
            if (x < 0 || x >= W_DIM) continue;
            if (yT >= 0 && targets[planeOff + yT * W_DIM + x] > 0) best = d2;
            if (yB < H_DIM && d2 < best && targets[planeOff + yB * W_DIM + x] > 0) best = d2;
        }
        const int xL = gw - r, xR = gw + r;
        for (int dy = -r + 1; dy <= r - 1; ++dy) {
            int d2 = rr + dy * dy;
            if (d2 >= best) continue;
            int y = gh + dy;
            if (y < 0 || y >= H_DIM) continue;
            if (xL >= 0 && targets[planeOff + y * W_DIM + xL] > 0) best = d2;
            if (xR < W_DIM && d2 < best && targets[planeOff + y * W_DIM + xR] > 0) best = d2;
        }
    }
    return best;
}

__device__ __forceinline__ float sqrt_approx(float v)
{
    float r;
    asm("sqrt.approx.f32 %0, %1;" : "=f"(r) : "f"(v));
    return r;
}

// Load one tile's raw data into registers.
// Warp w owns mask row w (all warps) and mask row 32+w (w < 16).
// av* lanes 0..31 -> cols w0-8+lane; bv* lanes 0..15 -> cols w0+24+lane.
__device__ __forceinline__ void load_tile(const float* __restrict__ logits,
                                          const int* __restrict__ targets,
                                          int planeOff, int h0, int w0,
                                          int w, int lane,
                                          float& x, int& a0, int& b0,
                                          int& a1, int& b1)
{
    x = logits[planeOff + (h0 + w) * W_DIM + (w0 + lane)];

    const int* rowBase = targets + planeOff;
    a0 = 0; b0 = 0; a1 = 0; b1 = 0;

    int g0 = h0 - HALO + w;                      // mask row w
    bool r0 = (g0 >= 0) && (g0 < H_DIM);
    int c0 = w0 - HALO + lane;
    if (r0 && c0 >= 0 && c0 < W_DIM) a0 = __ldg(rowBase + g0 * W_DIM + c0);
    int c1 = w0 + 24 + lane;
    if (r0 && lane < 16 && c1 < W_DIM) b0 = __ldg(rowBase + g0 * W_DIM + c1);

    if (w < 16) {
        int g1 = h0 - HALO + 32 + w;             // mask row 32+w
        bool r1 = (g1 >= 0) && (g1 < H_DIM);
        if (r1 && c0 >= 0 && c0 < W_DIM) a1 = __ldg(rowBase + g1 * W_DIM + c0);
        if (r1 && lane < 16 && c1 < W_DIM) b1 = __ldg(rowBase + g1 * W_DIM + c1);
    }
}

// Horizontal nearest-dx^2 for one mask row from ballot-assembled bits.
__device__ __forceinline__ int horiz_dxsq(int a, int b, int lane)
{
    unsigned int lo = __ballot_sync(0xffffffffu, a > 0);
    unsigned int hi = __ballot_sync(0xffffffffu, b > 0);  // lanes>=16 give 0
    unsigned int win = __funnelshift_r(lo, hi, lane) & 0x1FFFFu;
    unsigned int comb = (win >> 8) | (__brev(win) >> 23);
    comb |= 0x800u;                               // sentinel dx=11 -> 121
    int dx = __ffs(comb) - 1;
    return dx * dx;
}

__global__ __launch_bounds__(1024, 1)
void edt_loss_kernel(const float* __restrict__ logits,
                     const int* __restrict__ targets,
                     float* __restrict__ out)
{
    __shared__ int s_dxsq[2][SROWS][32];          // double-buffered, 12 KB
    __shared__ float s_warp[32];

    const int tid  = threadIdx.x;                 // 0..1023
    const int lane = tid & 31;
    const int w    = tid >> 5;                    // warp 0..31 == pixel row

    // ---- Decode + prologue load of first tile ----
    int t = blockIdx.x;                           // tiles t, t+148, t+296
    int bz = t / 100, rm = t - bz * 100;
    int by = rm / 10, bx = rm - by * 10;
    int planeOff = bz * (H_DIM * W_DIM);
    int h0 = by * TILE, w0 = bx * TILE;

    float x; int a0, b0, a1, b1;
    load_tile(logits, targets, planeOff, h0, w0, w, lane, x, a0, b0, a1, b1);

    float acc = 0.0f;
    int buf = 0;

    for (;;) {
        // ---- Horizontal pass for current tile -> s_dxsq[buf] ----
        s_dxsq[buf][w][lane] = horiz_dxsq(a0, b0, lane);
        if (w < 16)
            s_dxsq[buf][32 + w][lane] = horiz_dxsq(a1, b1, lane);

        // ---- Save current tile coords; prefetch next tile (hides LDG) ----
        float xc = x;
        int pc = planeOff, hc = h0, wc = w0;
        int tn = t + NCTA;
        bool more = (tn < NTILES);
        if (more) {
            bz = tn / 100; rm = tn - bz * 100;
            by = rm / 10; bx = rm - by * 10;
            planeOff = bz * (H_DIM * W_DIM);
            h0 = by * TILE; w0 = bx * TILE;
            load_tile(logits, targets, planeOff, h0, w0, w, lane,
                      x, a0, b0, a1, b1);
        }
        __syncthreads();                          // buf ready for all warps

        // ---- Vertical min-plus for pixel (row w, col lane) ----
        const int* c = &s_dxsq[buf][w][lane];     // window rows w .. w+16
        int best = c[8 * 32];
        #pragma unroll
        for (int d = 1; d <= 8; ++d)
            best = min(best, min(c[(8 - d) * 32], c[(8 + d) * 32]) + d * d);

        if (best > 81) {
            // Window min < 121 is a real seed distance -> valid upper bound;
            // >= 121 may be all-sentinel -> INF bound. Exact either way.
            int bound = (best < 121) ? best : 0x3fffffff;
            best = global_ring_search(targets, pc, hc + w, wc + lane, bound);
        }

        // p*d + (1-p) = p*(d-1) + 1; +1/pixel folded in at the end.
        float p = __fdividef(1.0f, 1.0f + __expf(-xc));
        acc = fmaf(p, sqrt_approx((float)best) - 1.0f, acc);

        if (!more) break;
        t = tn;
        buf ^= 1;
    }

    // ---- One block reduction per CTA (fixed order -> deterministic) ----
    #pragma unroll
    for (int off = 16; off > 0; off >>= 1)
        acc += __shfl_down_sync(0xffffffffu, acc, off);
    if (lane == 0) s_warp[w] = acc;
    __syncthreads();
    if (w == 0) {
        float v = s_warp[lane];                   // 32 warps exactly
        #pragma unroll
        for (int off = 16; off > 0; off >>= 1)
            v += __shfl_down_sync(0xffffffffu, v, off);
        if (lane == 0) {
            // Signed Q24 fixed point via two's-complement u64 atomics:
            // integer adds are associative -> bit-deterministic.
            long long q = (long long)((double)v * FP_SCALE);
            atomicAdd(&g_sum, (unsigned long long)q);
            unsigned int a;
            asm volatile("atom.acq_rel.gpu.global.add.u32 %0, [%1], %2;"
                         : "=r"(a) : "l"(&g_arrived), "r"(1u) : "memory");
            if (a == (unsigned int)(NCTA - 1)) {
                unsigned long long s;
                asm volatile("ld.global.cg.u64 %0, [%1];"
                             : "=l"(s) : "l"(&g_sum) : "memory");
                double mean = (double)(long long)s / (FP_SCALE * (double)N_TOTAL);
                out[0] = (float)(mean + 1.0);
                g_sum = 0ull;                     // reset for next graph replay
                g_arrived = 0;
            }
        }
    }
}

extern "C" void kernel_launch(void* const* d_in, const int* in_sizes, int n_in,
                              void* d_out, int out_size)
{
    const float* logits  = (const float*)d_in[0];
    const int*   targets = (const int*)d_in[1];
    float* out = (float*)d_out;

    edt_loss_kernel<<<NCTA, 1024>>>(logits, targets, out);
}

// round 15
// speedup vs baseline: 1.2271x; 1.2271x over previous
#include <cuda_runtime.h>
#include <cuda_bf16.h>
#include <math.h>

// Problem constants (fixed by dataset: B=4, H=W=320)
#define H_DIM 320
#define W_DIM 320
#define B_DIM 4
#define TILE 32                 // tile is 32x32 pixels
#define BLK_Y 16                // 32x16 threads, 2 pixels per thread
#define HALO 8
#define SROWS (TILE + 2 * HALO) // 48 mask rows
#define NBLK_X (W_DIM / TILE)   // 10
#define NBLK_Y (H_DIM / TILE)   // 10
#define NBLOCKS (NBLK_X * NBLK_Y * B_DIM) // 400
#define N_TOTAL (B_DIM * H_DIM * W_DIM)
#define FP_SCALE 16777216.0     // 2^24 fixed point (associative int adds)

__device__ unsigned long long g_sum = 0ull;   // two's-complement signed Q24
__device__ unsigned int g_arrived = 0;

// Exact global fallback. `best` on entry must be a valid upper bound
// (a real seed distance, or INF). Searches all rings r >= HALO+1.
__device__ __noinline__ int global_ring_search(const int* __restrict__ targets,
                                               int planeOff, int gh, int gw, int best)
{
    for (int r = HALO + 1; r < H_DIM + W_DIM; ++r) {
        if (r * r >= best) break;
        const int rr = r * r;
        const int yT = gh - r, yB = gh + r;
        for (int dx = -r; dx <= r; ++dx) {
            int d2 = rr + dx * dx;
            if (d2 >= best) continue;
            int x = gw + dx;
            if (x < 0 || x >= W_DIM) continue;
            if (yT >= 0 && targets[planeOff + yT * W_DIM + x] > 0) best = d2;
            if (yB < H_DIM && d2 < best && targets[planeOff + yB * W_DIM + x] > 0) best = d2;
        }
        const int xL = gw - r, xR = gw + r;
        for (int dy = -r + 1; dy <= r - 1; ++dy) {
            int d2 = rr + dy * dy;
            if (d2 >= best) continue;
            int y = gh + dy;
            if (y < 0 || y >= H_DIM) continue;
            if (xL >= 0 && targets[planeOff + y * W_DIM + xL] > 0) best = d2;
            if (xR < W_DIM && d2 < best && targets[planeOff + y * W_DIM + xR] > 0) best = d2;
        }
    }
    return best;
}

// Fused vertical min-plus for two vertically adjacent pixels (centers r, r+1).
// Rolling 2-register window: 18 LDS + ~50 ALU for BOTH pixels.
__device__ __forceinline__ void vertical_min_pair(const int* __restrict__ col,
                                                  int r, int& best0, int& best1)
{
    const int* c = col + r * 32;                // row (r+k) at c[32*k]
    int prev_up = c[0];                         // v[r - (d-1)] after step d-1
    int prev_dn = c[32];                        // v[r + d]     after step d-1
    int b0 = prev_up, b1 = prev_dn;
    #pragma unroll
    for (int d = 1; d <= 8; ++d) {
        int nu = c[-d * 32];                    // v[r - d]
        int nd = c[(d + 1) * 32];               // v[r + 1 + d]
        b0 = min(b0, min(nu, prev_dn) + d * d); // pixel0 rows r-d, r+d
        b1 = min(b1, min(prev_up, nd) + d * d); // pixel1 rows r+1-d, r+1+d
        prev_up = nu;
        prev_dn = nd;
    }
    best0 = b0;
    best1 = b1;
}

__device__ __forceinline__ float sqrt_approx(float v)
{
    float r;
    asm("sqrt.approx.f32 %0, %1;" : "=f"(r) : "f"(v));
    return r;
}

// sigmoid(x) = 0.5 * tanh(x/2) + 0.5 — single-MUFU tanh.approx (sm_75+).
__device__ __forceinline__ float sigmoid_fast(float x)
{
    float t;
    asm("tanh.approx.f32 %0, %1;" : "=f"(t) : "f"(0.5f * x));
    return fmaf(0.5f, t, 0.5f);
}

__global__ __launch_bounds__(512, 3)
void edt_loss_kernel(const float* __restrict__ logits,
                     const int* __restrict__ targets,
                     float* __restrict__ out)
{
    __shared__ int s_dxsq[SROWS][32];    // nearest dx^2 per (mask row, col); 6 KB
    __shared__ long long s_qsum;         // block sum, signed Q24 (associative)

    const int tx   = threadIdx.x;                 // 0..31 (== lane)
    const int ty   = threadIdx.y;                 // 0..15 (== warp)
    const int warp = ty;
    const int lane = tx;
    const int h0 = blockIdx.y * TILE;
    const int w0 = blockIdx.x * TILE;
    const int planeOff = blockIdx.z * (H_DIM * W_DIM);
    const int gw = w0 + tx;

    if (tx == 0 && ty == 0) s_qsum = 0ll;

    // ---- Hoist ALL global loads: one memory round, full MLP ----
    // Warp ty owns pixel rows 2ty and 2ty+1.
    float x0 = logits[planeOff + (h0 + 2 * ty) * W_DIM + gw];
    float x1 = logits[planeOff + (h0 + 2 * ty + 1) * W_DIM + gw];

    const int* rowBase = targets + planeOff;
    int av[3], bv[3];
    const bool interior = (blockIdx.x != 0) && (blockIdx.x != NBLK_X - 1) &&
                          (blockIdx.y != 0) && (blockIdx.y != NBLK_Y - 1);
    if (interior) {
        // No guards. bv loads cols 32..63 of the halo frame; the funnelshift
        // only ever consumes bits lane..lane+16 <= 47 of the assembled mask,
        // so lanes 16..31 loading in-bounds junk columns is harmless.
        const int* rp = rowBase + (h0 - HALO + warp) * W_DIM + (w0 - HALO);
        #pragma unroll
        for (int k = 0; k < 3; ++k) {
            av[k] = __ldg(rp + k * 16 * W_DIM + lane);
            bv[k] = __ldg(rp + k * 16 * W_DIM + 32 + lane);
        }
    } else {
        #pragma unroll
        for (int k = 0; k < 3; ++k) {
            av[k] = 0; bv[k] = 0;
            int grow = h0 - HALO + warp + k * 16;     // 0..47 -> global row
            bool rv = (grow >= 0) && (grow < H_DIM);
            int c0 = w0 - HALO + lane;
            if (rv && c0 >= 0 && c0 < W_DIM) av[k] = __ldg(rowBase + grow * W_DIM + c0);
            int c1 = w0 + 24 + lane;
            if (rv && lane < 16 && c1 < W_DIM)  bv[k] = __ldg(rowBase + grow * W_DIM + c1);
        }
    }

    // ---- Sigmoids early (1 MUFU each): overlap with ballot phase ----
    float p0 = sigmoid_fast(x0);
    float p1 = sigmoid_fast(x1);

    // ---- Ballot + funnelshift/brev/ffs horizontal nearest-dx^2 pass ----
    #pragma unroll
    for (int k = 0; k < 3; ++k) {
        unsigned int lo = __ballot_sync(0xffffffffu, av[k] > 0);
        unsigned int hi = __ballot_sync(0xffffffffu, bv[k] > 0);
        // 17-bit window = bits lane..lane+16 of (hi:lo)
        unsigned int win = __funnelshift_r(lo, hi, lane) & 0x1FFFFu;
        // bit d of comb = seed at dx=+d or dx=-d
        unsigned int comb = (win >> 8) | (__brev(win) >> 23);
        comb |= 0x800u;                            // sentinel dx=11 -> 121 (>81)
        int dx = __ffs(comb) - 1;
        s_dxsq[warp + k * 16][lane] = dx * dx;
    }
    __syncthreads();

    // ---- Fused vertical pass for the pixel pair + loss (FP32) ----
    const int* col = &s_dxsq[0][tx];
    int best0, best1;
    vertical_min_pair(col, 2 * ty + HALO, best0, best1);
    if (best0 > 81) {
        // Window min < 121 is a real seed distance -> valid upper bound;
        // >= 121 may be all-sentinel -> INF bound. Exact either way.
        int bnd = (best0 < 121) ? best0 : 0x3fffffff;
        best0 = global_ring_search(targets, planeOff, h0 + 2 * ty, gw, bnd);
    }
    if (best1 > 81) {
        int bnd = (best1 < 121) ? best1 : 0x3fffffff;
        best1 = global_ring_search(targets, planeOff, h0 + 2 * ty + 1, gw, bnd);
    }

    // p*d + (1-p) = p*(d-1) + 1; the +1/pixel is folded in analytically at
    // the end (out = mean + 1), so accumulate only p*(d-1).
    float acc = p0 * (sqrt_approx((float)best0) - 1.0f)
              + p1 * (sqrt_approx((float)best1) - 1.0f);

    // ---- Warp reduce (fixed order), then associative integer block sum ----
    #pragma unroll
    for (int off = 16; off > 0; off >>= 1)
        acc += __shfl_down_sync(0xffffffffu, acc, off);
    if (lane == 0) {
        // Q24 per-warp contribution; integer adds are associative ->
        // deterministic regardless of warp arrival order.
        long long q = (long long)((double)acc * FP_SCALE);
        atomicAdd((unsigned long long*)&s_qsum, (unsigned long long)q);
    }
    __syncthreads();

    if (tx == 0 && ty == 0) {
        atomicAdd(&g_sum, (unsigned long long)s_qsum);
        unsigned int t;
        asm volatile("atom.acq_rel.gpu.global.add.u32 %0, [%1], %2;"
                     : "=r"(t) : "l"(&g_arrived), "r"(1u) : "memory");
        if (t == (unsigned int)(NBLOCKS - 1)) {
            unsigned long long s;
            asm volatile("ld.global.cg.u64 %0, [%1];"
                         : "=l"(s) : "l"(&g_sum) : "memory");
            double mean = (double)(long long)s / (FP_SCALE * (double)N_TOTAL);
            out[0] = (float)(mean + 1.0);
            g_sum = 0ull;        // reset for next graph replay
            g_arrived = 0;
        }
    }
}

extern "C" void kernel_launch(void* const* d_in, const int* in_sizes, int n_in,
                              void* d_out, int out_size)
{
    const float* logits  = (const float*)d_in[0];
    const int*   targets = (const int*)d_in[1];
    float* out = (float*)d_out;

    dim3 block(32, BLK_Y, 1);
    dim3 grid(NBLK_X, NBLK_Y, B_DIM);
    edt_loss_kernel<<<grid, block>>>(logits, targets, out);
}

// round 16
// speedup vs baseline: 1.2362x; 1.0074x over previous
#include <cuda_runtime.h>
#include <cuda_bf16.h>
#include <math.h>

// Problem constants (fixed by dataset: B=4, H=W=320)
#define H_DIM 320
#define W_DIM 320
#define B_DIM 4
#define TILE 32                 // tile is 32x32 pixels
#define BLK_Y 16                // 32x16 threads, 2 pixels per thread
#define HALO 8
#define SROWS (TILE + 2 * HALO) // 48 mask rows
#define NBLK_X (W_DIM / TILE)   // 10
#define NBLK_Y (H_DIM / TILE)   // 10
#define NBLOCKS (NBLK_X * NBLK_Y * B_DIM) // 400
#define N_TOTAL (B_DIM * H_DIM * W_DIM)
#define FP_SCALE 16777216.0     // 2^24 fixed point (associative int adds)

__device__ unsigned long long g_sum = 0ull;   // two's-complement signed Q24
__device__ unsigned int g_arrived = 0;

// Exact global fallback. `best` on entry must be a valid upper bound
// (a real seed distance, or INF). Searches all rings r >= HALO+1.
__device__ __noinline__ int global_ring_search(const int* __restrict__ targets,
                                               int planeOff, int gh, int gw, int best)
{
    for (int r = HALO + 1; r < H_DIM + W_DIM; ++r) {
        if (r * r >= best) break;
        const int rr = r * r;
        const int yT = gh - r, yB = gh + r;
        for (int dx = -r; dx <= r; ++dx) {
            int d2 = rr + dx * dx;
            if (d2 >= best) continue;
            int x = gw + dx;
            if (x < 0 || x >= W_DIM) continue;
            if (yT >= 0 && targets[planeOff + yT * W_DIM + x] > 0) best = d2;
            if (yB < H_DIM && d2 < best && targets[planeOff + yB * W_DIM + x] > 0) best = d2;
        }
        const int xL = gw - r, xR = gw + r;
        for (int dy = -r + 1; dy <= r - 1; ++dy) {
            int d2 = rr + dy * dy;
            if (d2 >= best) continue;
            int y = gh + dy;
            if (y < 0 || y >= H_DIM) continue;
            if (xL >= 0 && targets[planeOff + y * W_DIM + xL] > 0) best = d2;
            if (xR < W_DIM && d2 < best && targets[planeOff + y * W_DIM + xR] > 0) best = d2;
        }
    }
    return best;
}

// Fused vertical min-plus for two vertically adjacent pixels (centers r, r+1).
// Rolling 2-register window: 18 LDS + ~50 ALU for BOTH pixels.
__device__ __forceinline__ void vertical_min_pair(const int* __restrict__ col,
                                                  int r, int& best0, int& best1)
{
    const int* c = col + r * 32;                // row (r+k) at c[32*k]
    int prev_up = c[0];                         // v[r - (d-1)] after step d-1
    int prev_dn = c[32];                        // v[r + d]     after step d-1
    int b0 = prev_up, b1 = prev_dn;
    #pragma unroll
    for (int d = 1; d <= 8; ++d) {
        int nu = c[-d * 32];                    // v[r - d]
        int nd = c[(d + 1) * 32];               // v[r + 1 + d]
        b0 = min(b0, min(nu, prev_dn) + d * d); // pixel0 rows r-d, r+d
        b1 = min(b1, min(prev_up, nd) + d * d); // pixel1 rows r+1-d, r+1+d
        prev_up = nu;
        prev_dn = nd;
    }
    best0 = b0;
    best1 = b1;
}

__device__ __forceinline__ float sqrt_approx(float v)
{
    float r;
    asm("sqrt.approx.f32 %0, %1;" : "=f"(r) : "f"(v));
    return r;
}

// sigmoid(x) = 0.5 * tanh(x/2) + 0.5 — single-MUFU tanh.approx (sm_75+).
__device__ __forceinline__ float sigmoid_fast(float x)
{
    float t;
    asm("tanh.approx.f32 %0, %1;" : "=f"(t) : "f"(0.5f * x));
    return fmaf(0.5f, t, 0.5f);
}

__global__ __launch_bounds__(512, 3)
void edt_loss_kernel(const float* __restrict__ logits,
                     const int* __restrict__ targets,
                     float* __restrict__ out)
{
    __shared__ int s_dxsq[SROWS][32];    // nearest dx^2 per (mask row, col); 6 KB
    __shared__ float s_warp[16];

    const int tx   = threadIdx.x;                 // 0..31 (== lane)
    const int ty   = threadIdx.y;                 // 0..15 (== warp)
    const int warp = ty;
    const int lane = tx;
    const int h0 = blockIdx.y * TILE;
    const int w0 = blockIdx.x * TILE;
    const int planeOff = blockIdx.z * (H_DIM * W_DIM);
    const int gw = w0 + tx;

    // ---- Hoist ALL global loads: one memory round, full MLP ----
    // Warp ty owns pixel rows 2ty and 2ty+1.
    float x0 = logits[planeOff + (h0 + 2 * ty) * W_DIM + gw];
    float x1 = logits[planeOff + (h0 + 2 * ty + 1) * W_DIM + gw];

    const int* rowBase = targets + planeOff;
    int av[3], bv[3];
    const bool interior = (blockIdx.x != 0) && (blockIdx.x != NBLK_X - 1) &&
                          (blockIdx.y != 0) && (blockIdx.y != NBLK_Y - 1);
    if (interior) {
        // No guards. bv loads cols 32..63 of the halo frame; the funnelshift
        // only ever consumes bits lane..lane+16 <= 47 of the assembled mask,
        // so lanes 16..31 loading in-bounds junk columns is harmless.
        const int* rp = rowBase + (h0 - HALO + warp) * W_DIM + (w0 - HALO);
        #pragma unroll
        for (int k = 0; k < 3; ++k) {
            av[k] = __ldg(rp + k * 16 * W_DIM + lane);
            bv[k] = __ldg(rp + k * 16 * W_DIM + 32 + lane);
        }
    } else {
        #pragma unroll
        for (int k = 0; k < 3; ++k) {
            av[k] = 0; bv[k] = 0;
            int grow = h0 - HALO + warp + k * 16;     // 0..47 -> global row
            bool rv = (grow >= 0) && (grow < H_DIM);
            int c0 = w0 - HALO + lane;
            if (rv && c0 >= 0 && c0 < W_DIM) av[k] = __ldg(rowBase + grow * W_DIM + c0);
            int c1 = w0 + 24 + lane;
            if (rv && lane < 16 && c1 < W_DIM)  bv[k] = __ldg(rowBase + grow * W_DIM + c1);
        }
    }

    // ---- Sigmoids early (1 MUFU each): overlap with ballot phase ----
    float p0 = sigmoid_fast(x0);
    float p1 = sigmoid_fast(x1);

    // ---- Ballot + funnelshift/brev/ffs horizontal nearest-dx^2 pass ----
    #pragma unroll
    for (int k = 0; k < 3; ++k) {
        unsigned int lo = __ballot_sync(0xffffffffu, av[k] > 0);
        unsigned int hi = __ballot_sync(0xffffffffu, bv[k] > 0);
        // 17-bit window = bits lane..lane+16 of (hi:lo)
        unsigned int win = __funnelshift_r(lo, hi, lane) & 0x1FFFFu;
        // bit d of comb = seed at dx=+d or dx=-d
        unsigned int comb = (win >> 8) | (__brev(win) >> 23);
        comb |= 0x800u;                            // sentinel dx=11 -> 121 (>81)
        int dx = __ffs(comb) - 1;
        s_dxsq[warp + k * 16][lane] = dx * dx;
    }
    __syncthreads();

    // ---- Fused vertical pass for the pixel pair + loss (FP32) ----
    const int* col = &s_dxsq[0][tx];
    int best0, best1;
    vertical_min_pair(col, 2 * ty + HALO, best0, best1);
    if (best0 > 81) {
        // Window min < 121 is a real seed distance -> valid upper bound;
        // >= 121 may be all-sentinel -> INF bound. Exact either way.
        int bnd = (best0 < 121) ? best0 : 0x3fffffff;
        best0 = global_ring_search(targets, planeOff, h0 + 2 * ty, gw, bnd);
    }
    if (best1 > 81) {
        int bnd = (best1 < 121) ? best1 : 0x3fffffff;
        best1 = global_ring_search(targets, planeOff, h0 + 2 * ty + 1, gw, bnd);
    }

    // p*d + (1-p) = p*(d-1) + 1; the +1/pixel is folded in analytically at
    // the end (out = mean + 1), so accumulate only p*(d-1).
    float acc = p0 * (sqrt_approx((float)best0) - 1.0f)
              + p1 * (sqrt_approx((float)best1) - 1.0f);

    // ---- Deterministic block reduction (FP32 shuffle tree, fixed order) ----
    #pragma unroll
    for (int off = 16; off > 0; off >>= 1)
        acc += __shfl_down_sync(0xffffffffu, acc, off);
    if (lane == 0) s_warp[warp] = acc;
    __syncthreads();
    if (warp == 0) {
        float v = (lane < 16) ? s_warp[lane] : 0.0f;
        #pragma unroll
        for (int off = 8; off > 0; off >>= 1)
            v += __shfl_down_sync(0xffffffffu, v, off);
        if (lane == 0) {
            // Signed Q24 fixed point via two's-complement u64 atomics:
            // integer adds are associative -> bit-deterministic.
            long long q = (long long)((double)v * FP_SCALE);
            atomicAdd(&g_sum, (unsigned long long)q);
            unsigned int t;
            asm volatile("atom.acq_rel.gpu.global.add.u32 %0, [%1], %2;"
                         : "=r"(t) : "l"(&g_arrived), "r"(1u) : "memory");
            if (t == (unsigned int)(NBLOCKS - 1)) {
                unsigned long long s;
                asm volatile("ld.global.cg.u64 %0, [%1];"
                             : "=l"(s) : "l"(&g_sum) : "memory");
                double mean = (double)(long long)s / (FP_SCALE * (double)N_TOTAL);
                out[0] = (float)(mean + 1.0);
                g_sum = 0ull;        // reset for next graph replay
                g_arrived = 0;
            }
        }
    }
}

extern "C" void kernel_launch(void* const* d_in, const int* in_sizes, int n_in,
                              void* d_out, int out_size)
{
    const float* logits  = (const float*)d_in[0];
    const int*   targets = (const int*)d_in[1];
    float* out = (float*)d_out;

    dim3 block(32, BLK_Y, 1);
    dim3 grid(NBLK_X, NBLK_Y, B_DIM);
    edt_loss_kernel<<<grid, block>>>(logits, targets, out);
}